// round 5
// baseline (speedup 1.0000x reference)
#include <cuda_runtime.h>
#include <cstdint>

// ---------------------------------------------------------------------------
// EEGConvNetMiniV3: GCN(128->16)+BN+LReLU -> SAGPool(0.5) -> GCN(16->32)+BN+
// LReLU -> SAGPool(0.5) -> global_add_pool -> MLP 32->8->4->2 (LReLU each).
// N=200000, E=6400000, single graph. edge_weigth unused (emask=1), b1/b2
// cancel inside BatchNorm. Aggregations are CSR "pull" (no float atomics).
// ---------------------------------------------------------------------------

#define NMAX  200000
#define EMAX  6400000
#define K1MAX 100000

// -------- static device scratch --------
__device__ float              g_hx1[NMAX * 16];   // x @ W1
__device__ float              g_h1 [NMAX * 16];   // pull-agg -> bn/lrelu in place
__device__ float              g_p1 [NMAX];        // h1 @ Wr1
__device__ float              g_s1 [NMAX];        // score1
__device__ unsigned long long g_key1[NMAX];
__device__ int                g_inv1[NMAX];
__device__ float              g_hx2[K1MAX * 32];  // pooled feats @ W2
__device__ float              g_h2 [K1MAX * 32];
__device__ float              g_p2 [K1MAX];
__device__ float              g_s2 [K1MAX];
__device__ unsigned long long g_key2[K1MAX];
__device__ int                g_src2[EMAX];
__device__ int                g_dst2[EMAX];
__device__ double             g_stats1[32];       // [sum(16) | sumsq(16)]
__device__ double             g_stats2[64];       // [sum(32) | sumsq(32)]
__device__ float              g_pooled[32];
__device__ int                g_n1;
__device__ int                g_e2;
__device__ unsigned int       g_hist[2][65536];

// CSR structures (in-edges, keyed by dst)
__device__ int g_deg1[NMAX],  g_row1[NMAX],  g_cur1[NMAX];
__device__ int g_eidx1[EMAX];                  // src node per CSR slot
__device__ int g_deg2[K1MAX], g_row2[K1MAX], g_cur2[K1MAX];
__device__ int g_eidx2[EMAX];
__device__ int g_alloc1, g_alloc2;

struct Sel {
    unsigned long long prefix;
    unsigned int       krem;
};
__device__ Sel g_sel[2];

// ---------------------------------------------------------------------------
__global__ void k_init(int N, int K1, int K2) {
    long long tid    = blockIdx.x * (long long)blockDim.x + threadIdx.x;
    long long stride = (long long)gridDim.x * blockDim.x;
    for (long long t = tid; t < N; t += stride) { g_inv1[t] = -1; g_deg1[t] = 0; }
    for (long long t = tid; t < K1; t += stride) g_deg2[t] = 0;
    for (long long t = tid; t < 131072; t += stride) ((unsigned*)g_hist)[t] = 0u;
    if (tid < 32)  g_stats1[tid] = 0.0;
    if (tid < 64)  g_stats2[tid] = 0.0;
    if (tid < 32)  g_pooled[tid] = 0.f;
    if (tid == 0) {
        g_n1 = 0; g_e2 = 0; g_alloc1 = 0; g_alloc2 = 0;
        g_sel[0].prefix = 0ull; g_sel[0].krem = (unsigned)K1;
        g_sel[1].prefix = 0ull; g_sel[1].krem = (unsigned)K2;
    }
}

// x (N x 128) @ W1 (128 x 16) -> g_hx1
__global__ __launch_bounds__(256) void k_gemm1(const float* __restrict__ x,
                                               const float* __restrict__ W1, int N) {
    __shared__ float sW[128 * 16];
    __shared__ float sX[16 * 128];
    int tid  = threadIdx.x;
    int row0 = blockIdx.x * 16;
    for (int j = tid; j < 2048; j += 256) sW[j] = W1[j];
    for (int j = tid; j < 2048; j += 256) {
        int r = j >> 7, c = j & 127;
        int row = row0 + r;
        sX[j] = (row < N) ? x[(long long)row * 128 + c] : 0.f;
    }
    __syncthreads();
    int r = tid >> 4, f = tid & 15;
    float acc = 0.f;
#pragma unroll 16
    for (int k = 0; k < 128; k++) acc += sX[r * 128 + k] * sW[k * 16 + f];
    int row = row0 + r;
    if (row < N) g_hx1[(long long)row * 16 + f] = acc;
}

// ---- CSR build: degree histogram, row allocation (block scan), scatter ----
__global__ __launch_bounds__(256) void k_deg1(const int* __restrict__ dst, int E) {
    int e = blockIdx.x * blockDim.x + threadIdx.x;
    if (e < E) atomicAdd(&g_deg1[dst[e]], 1);
}

// which=0: stage-1 arrays; which=1: stage-2. All device-symbol refs in device code.
__global__ __launch_bounds__(256) void k_rows(int which, int n) {
    const int* deg   = which ? g_deg2 : g_deg1;
    int*       row   = which ? g_row2 : g_row1;
    int*       cur   = which ? g_cur2 : g_cur1;
    int*       alloc = which ? &g_alloc2 : &g_alloc1;
    __shared__ int sc[256];
    __shared__ int sbase;
    int tid = threadIdx.x;
    int i   = blockIdx.x * 256 + tid;
    int d   = (i < n) ? deg[i] : 0;
    sc[tid] = d;
    __syncthreads();
    for (int off = 1; off < 256; off <<= 1) {
        int v = (tid >= off) ? sc[tid - off] : 0;
        __syncthreads();
        sc[tid] += v;
        __syncthreads();
    }
    if (tid == 255) sbase = atomicAdd(alloc, sc[255]);
    __syncthreads();
    if (i < n) {
        int r = sbase + sc[tid] - d;
        row[i] = r;
        cur[i] = r;
    }
}

__global__ __launch_bounds__(256) void k_scatter1(const int* __restrict__ src,
                                                  const int* __restrict__ dst, int E) {
    int e = blockIdx.x * blockDim.x + threadIdx.x;
    if (e >= E) return;
    int pos = atomicAdd(&g_cur1[dst[e]], 1);
    g_eidx1[pos] = src[e];
}

// ---- pull aggregation, F=16: warp per node, 16 lanes x 2 edges ----
__global__ __launch_bounds__(256) void k_pullagg16(int N) {
    int warp = (blockIdx.x * blockDim.x + threadIdx.x) >> 5;
    if (warp >= N) return;
    int lane = threadIdx.x & 31;
    int f    = lane & 15;
    int half = lane >> 4;
    int beg  = g_row1[warp];
    int deg  = g_deg1[warp];
    float acc = 0.f;
    for (int j = half; j < deg; j += 2) {
        int s = g_eidx1[beg + j];
        acc += g_hx1[s * 16 + f];
    }
    acc += __shfl_xor_sync(0xFFFFFFFFu, acc, 16);
    if (lane < 16) g_h1[warp * 16 + f] = acc;
}

// BN stats: feature fixed per thread, strided rows
template <int F>
__global__ __launch_bounds__(256) void k_bnstats(int n) {
    const float* h     = (F == 16) ? g_h1 : g_h2;
    double*      stats = (F == 16) ? g_stats1 : g_stats2;
    int tid = threadIdx.x;
    int f   = tid % F;
    const int rpb = 256 / F;
    float s = 0.f, sq = 0.f;
    for (long long row = blockIdx.x * (long long)rpb + tid / F; row < n;
         row += (long long)gridDim.x * rpb) {
        float v = h[row * F + f];
        s += v; sq += v * v;
    }
    __shared__ float sh[256], shq[256];
    sh[tid] = s; shq[tid] = sq;
    __syncthreads();
    if (tid < F) {
        float a = 0.f, b = 0.f;
        for (int j = tid; j < 256; j += F) { a += sh[j]; b += shq[j]; }
        atomicAdd(&stats[f],     (double)a);
        atomicAdd(&stats[F + f], (double)b);
    }
}

// BN (training stats) + LeakyReLU in place, plus score precomputation:
//   p[i] = h[i] @ Wr,  s[i] = h[i] @ Wroot + br (edge part added by pullscore)
template <int F>
__global__ __launch_bounds__(256) void k_bnapply(int n,
                                                 const float* __restrict__ gam,
                                                 const float* __restrict__ beta,
                                                 const float* __restrict__ Wr,
                                                 const float* __restrict__ br,
                                                 const float* __restrict__ Wroot) {
    float*  h     = (F == 16) ? g_h1 : g_h2;
    float*  p     = (F == 16) ? g_p1 : g_p2;
    float*  s     = (F == 16) ? g_s1 : g_s2;
    double* stats = (F == 16) ? g_stats1 : g_stats2;

    __shared__ float smu[F], ssc[F], sbe[F], sWr[F], sWt[F];
    if (threadIdx.x < F) {
        int    f   = threadIdx.x;
        double mu  = stats[f] / (double)n;
        double var = stats[F + f] / (double)n - mu * mu;
        smu[f] = (float)mu;
        ssc[f] = gam[f] * rsqrtf((float)var + 1e-5f);
        sbe[f] = beta[f];
        sWr[f] = Wr[f];
        sWt[f] = Wroot[f];
    }
    __syncthreads();
    long long i = blockIdx.x * (long long)blockDim.x + threadIdx.x;
    if (i >= n) return;
    float dotp = 0.f, dotr = 0.f;
#pragma unroll
    for (int f = 0; f < F; f++) {
        float v = h[i * F + f];
        v = (v - smu[f]) * ssc[f] + sbe[f];
        v = v > 0.f ? v : 0.01f * v;
        h[i * F + f] = v;
        dotp += v * sWr[f];
        dotr += v * sWt[f];
    }
    p[i] = dotp;
    s[i] = dotr + br[0];
}

// pull scalar score: s[i] += sum over in-edges of p[src]
__global__ __launch_bounds__(256) void k_pullscore1(int N) {
    int warp = (blockIdx.x * blockDim.x + threadIdx.x) >> 5;
    if (warp >= N) return;
    int lane = threadIdx.x & 31;
    int beg  = g_row1[warp];
    int deg  = g_deg1[warp];
    float acc = 0.f;
    for (int j = lane; j < deg; j += 32) acc += g_p1[g_eidx1[beg + j]];
#pragma unroll
    for (int o = 16; o; o >>= 1) acc += __shfl_xor_sync(0xFFFFFFFFu, acc, o);
    if (lane == 0) g_s1[warp] += acc;
}

// pass 0 of radix select fused with key construction
__global__ __launch_bounds__(256) void k_keyhist0(int which, int n) {
    const float*        s    = which ? g_s2 : g_s1;
    unsigned long long* key  = which ? g_key2 : g_key1;
    unsigned*           hist = g_hist[which];
    for (long long i = blockIdx.x * (long long)blockDim.x + threadIdx.x; i < n;
         i += (long long)gridDim.x * blockDim.x) {
        unsigned u = __float_as_uint(s[i]);
        u = (u & 0x80000000u) ? ~u : (u | 0x80000000u);
        unsigned long long k =
            ((unsigned long long)u << 32) | (unsigned long long)(0xFFFFFFFFu - (unsigned)i);
        key[i] = k;
        atomicAdd(&hist[(unsigned)(k >> 48)], 1u);
    }
}

// passes 1..3: histogram of next 16 bits among prefix-matching keys
__global__ __launch_bounds__(256) void k_hist16(int which, int n, int pass) {
    const unsigned long long* key  = which ? g_key2 : g_key1;
    unsigned*                 hist = g_hist[which];
    unsigned long long prefix = g_sel[which].prefix;
    int                shift  = 48 - 16 * pass;
    unsigned long long mask   = ~0ull << (64 - 16 * pass);
    for (long long i = blockIdx.x * (long long)blockDim.x + threadIdx.x; i < n;
         i += (long long)gridDim.x * blockDim.x) {
        unsigned long long k = key[i];
        if (((k ^ prefix) & mask) == 0ull)
            atomicAdd(&hist[(unsigned)(k >> shift) & 0xFFFFu], 1u);
    }
}

__global__ __launch_bounds__(1024) void k_scan16(int which, int pass) {
    __shared__ unsigned part[1024];
    Sel*      S    = &g_sel[which];
    unsigned* hist = g_hist[which];
    int t = threadIdx.x;
    unsigned krem = S->krem;

    unsigned own = 0;
#pragma unroll 4
    for (int j = 0; j < 64; j++) own += hist[t * 64 + j];
    part[t] = own;
    __syncthreads();
    for (int off = 1; off < 1024; off <<= 1) {
        unsigned add = (t + off < 1024) ? part[t + off] : 0u;
        __syncthreads();
        part[t] += add;
        __syncthreads();
    }
    unsigned suf_incl = part[t];
    unsigned suf_excl = suf_incl - own;
    if (suf_incl >= krem && suf_excl < krem) {
        unsigned acc = suf_excl;
        int chosen = 0; unsigned newkrem = krem;
        for (int j = 63; j >= 0; --j) {
            unsigned c = hist[t * 64 + j];
            if (acc + c >= krem) { chosen = t * 64 + j; newkrem = krem - acc; break; }
            acc += c;
        }
        S->prefix |= ((unsigned long long)chosen) << (48 - 16 * pass);
        S->krem = newkrem;
    }
#pragma unroll 4
    for (int j = 0; j < 64; j++) hist[t * 64 + j] = 0u;
}

// keep key >= threshold; hk = h1*tanh(s1); hx2 = hk @ W2 (fused); warp-agg cursor
__global__ __launch_bounds__(256) void k_compact_nodes(const float* __restrict__ W2, int N) {
    __shared__ float sW[16 * 32];
    for (int j = threadIdx.x; j < 512; j += 256) sW[j] = W2[j];
    __syncthreads();
    int i    = blockIdx.x * blockDim.x + threadIdx.x;
    int lane = threadIdx.x & 31;
    bool keep = (i < N) && (g_key1[i] >= g_sel[0].prefix);
    unsigned m = __ballot_sync(0xFFFFFFFFu, keep);
    int base = 0;
    if (lane == 0 && m) base = atomicAdd(&g_n1, __popc(m));
    base = __shfl_sync(0xFFFFFFFFu, base, 0);
    if (!keep) return;
    int pos = base + __popc(m & ((1u << lane) - 1u));
    g_inv1[i] = pos;
    float tn = tanhf(g_s1[i]);
    float hk[16];
#pragma unroll
    for (int f = 0; f < 16; f++) hk[f] = g_h1[(long long)i * 16 + f] * tn;
#pragma unroll
    for (int o = 0; o < 32; o++) {
        float acc = 0.f;
#pragma unroll
        for (int f = 0; f < 16; f++) acc += hk[f] * sW[f * 32 + o];
        g_hx2[(long long)pos * 32 + o] = acc;
    }
}

// compact surviving edges (renumbered), warp-aggregated cursor
__global__ __launch_bounds__(256) void k_compact_edges(const int* __restrict__ src,
                                                       const int* __restrict__ dst, int E) {
    int e    = blockIdx.x * blockDim.x + threadIdx.x;
    int lane = threadIdx.x & 31;
    int ns = -1, nd = -1;
    if (e < E) { ns = g_inv1[src[e]]; nd = g_inv1[dst[e]]; }
    bool keep = (ns | nd) >= 0;
    unsigned m = __ballot_sync(0xFFFFFFFFu, keep);
    int base = 0;
    if (lane == 0 && m) base = atomicAdd(&g_e2, __popc(m));
    base = __shfl_sync(0xFFFFFFFFu, base, 0);
    if (keep) {
        int pos = base + __popc(m & ((1u << lane) - 1u));
        g_src2[pos] = ns;
        g_dst2[pos] = nd;
    }
}

__global__ __launch_bounds__(256) void k_deg2() {
    int E2 = g_e2;
    for (int e = blockIdx.x * blockDim.x + threadIdx.x; e < E2;
         e += gridDim.x * blockDim.x)
        atomicAdd(&g_deg2[g_dst2[e]], 1);
}

__global__ __launch_bounds__(256) void k_scatter2() {
    int E2 = g_e2;
    for (int e = blockIdx.x * blockDim.x + threadIdx.x; e < E2;
         e += gridDim.x * blockDim.x) {
        int pos = atomicAdd(&g_cur2[g_dst2[e]], 1);
        g_eidx2[pos] = g_src2[e];
    }
}

// pull aggregation, F=32: warp per node, lane = feature
__global__ __launch_bounds__(256) void k_pullagg32(int K1) {
    int warp = (blockIdx.x * blockDim.x + threadIdx.x) >> 5;
    if (warp >= K1) return;
    int lane = threadIdx.x & 31;
    int beg  = g_row2[warp];
    int deg  = g_deg2[warp];
    float acc = 0.f;
    for (int j = 0; j < deg; j++) {
        int s = g_eidx2[beg + j];
        acc += g_hx2[s * 32 + lane];
    }
    g_h2[warp * 32 + lane] = acc;
}

__global__ __launch_bounds__(256) void k_pullscore2(int K1) {
    int warp = (blockIdx.x * blockDim.x + threadIdx.x) >> 5;
    if (warp >= K1) return;
    int lane = threadIdx.x & 31;
    int beg  = g_row2[warp];
    int deg  = g_deg2[warp];
    float acc = 0.f;
    for (int j = lane; j < deg; j += 32) acc += g_p2[g_eidx2[beg + j]];
#pragma unroll
    for (int o = 16; o; o >>= 1) acc += __shfl_xor_sync(0xFFFFFFFFu, acc, o);
    if (lane == 0) g_s2[warp] += acc;
}

// sum over kept stage-2 nodes of h2 * tanh(s2) -> g_pooled[32]
__global__ __launch_bounds__(256) void k_pool(int K1) {
    __shared__ float part[32];
    if (threadIdx.x < 32) part[threadIdx.x] = 0.f;
    __syncthreads();
    unsigned long long T = g_sel[1].prefix;
    int   g = threadIdx.x & 7;
    float a0 = 0.f, a1 = 0.f, a2 = 0.f, a3 = 0.f;
    long long total  = (long long)K1 * 8;
    long long stride = (long long)gridDim.x * blockDim.x;
    for (long long t = blockIdx.x * (long long)blockDim.x + threadIdx.x; t < total;
         t += stride) {
        long long i = t >> 3;
        if (g_key2[i] >= T) {
            float  tn = tanhf(g_s2[i]);
            float4 v  = ((const float4*)g_h2)[t];
            a0 += v.x * tn; a1 += v.y * tn; a2 += v.z * tn; a3 += v.w * tn;
        }
    }
    atomicAdd(&part[g * 4 + 0], a0);
    atomicAdd(&part[g * 4 + 1], a1);
    atomicAdd(&part[g * 4 + 2], a2);
    atomicAdd(&part[g * 4 + 3], a3);
    __syncthreads();
    if (threadIdx.x < 32) atomicAdd(&g_pooled[threadIdx.x], part[threadIdx.x]);
}

__global__ void k_mlp(const float* __restrict__ fw1, const float* __restrict__ fb1,
                      const float* __restrict__ fw2, const float* __restrict__ fb2,
                      const float* __restrict__ fw3, const float* __restrict__ fb3,
                      float* __restrict__ out) {
    if (threadIdx.x == 0 && blockIdx.x == 0) {
        float a[8], b[4];
#pragma unroll
        for (int o = 0; o < 8; o++) {
            float v = fb1[o];
            for (int j = 0; j < 32; j++) v += g_pooled[j] * fw1[j * 8 + o];
            a[o] = v > 0.f ? v : 0.01f * v;
        }
#pragma unroll
        for (int o = 0; o < 4; o++) {
            float v = fb2[o];
            for (int j = 0; j < 8; j++) v += a[j] * fw2[j * 4 + o];
            b[o] = v > 0.f ? v : 0.01f * v;
        }
#pragma unroll
        for (int o = 0; o < 2; o++) {
            float v = fb3[o];
            for (int j = 0; j < 4; j++) v += b[j] * fw3[j * 2 + o];
            out[o] = v > 0.f ? v : 0.01f * v;
        }
    }
}

// ---------------------------------------------------------------------------
extern "C" void kernel_launch(void* const* d_in, const int* in_sizes, int n_in,
                              void* d_out, int out_size) {
    const float* x   = (const float*)d_in[0];
    const int*   ei  = (const int*)d_in[1];
    int          E   = in_sizes[2];      // edge_weigth count
    int          N   = in_sizes[3];      // batch count
    const int*   src = ei;
    const int*   dst = ei + E;
    int K1 = (N + 1) / 2;

    const float* W1     = (const float*)d_in[4];
    const float* g1     = (const float*)d_in[6];
    const float* be1    = (const float*)d_in[7];
    const float* Wr1    = (const float*)d_in[8];
    const float* br1    = (const float*)d_in[9];
    const float* Wroot1 = (const float*)d_in[10];
    const float* W2     = (const float*)d_in[11];
    const float* g2     = (const float*)d_in[13];
    const float* be2    = (const float*)d_in[14];
    const float* Wr2    = (const float*)d_in[15];
    const float* br2    = (const float*)d_in[16];
    const float* Wroot2 = (const float*)d_in[17];
    const float* fw1    = (const float*)d_in[18];
    const float* fb1    = (const float*)d_in[19];
    const float* fw2    = (const float*)d_in[20];
    const float* fb2    = (const float*)d_in[21];
    const float* fw3    = (const float*)d_in[22];
    const float* fb3    = (const float*)d_in[23];
    float*       out    = (float*)d_out;

    int nb_e = (E + 255) / 256;
    int nb_n = (N + 255) / 256;
    int K2   = (K1 + 1) / 2;

    // ---- init + stage-1 GEMM ----
    k_init<<<1024, 256>>>(N, K1, K2);
    k_gemm1<<<(N + 15) / 16, 256>>>(x, W1, N);

    // ---- CSR build (stage 1) ----
    k_deg1<<<nb_e, 256>>>(dst, E);
    k_rows<<<nb_n, 256>>>(0, N);
    k_scatter1<<<nb_e, 256>>>(src, dst, E);

    // ---- stage 1: pull-agg + BN + LReLU ----
    k_pullagg16<<<(N * 32 + 255) / 256, 256>>>(N);
    k_bnstats<16><<<512, 256>>>(N);
    k_bnapply<16><<<nb_n, 256>>>(N, g1, be1, Wr1, br1, Wroot1);

    // ---- stage 1 score + top-k select ----
    k_pullscore1<<<(N * 32 + 255) / 256, 256>>>(N);
    k_keyhist0<<<256, 256>>>(0, N);
    k_scan16<<<1, 1024>>>(0, 0);
    for (int p = 1; p < 4; p++) {
        k_hist16<<<128, 256>>>(0, N, p);
        k_scan16<<<1, 1024>>>(0, p);
    }
    k_compact_nodes<<<nb_n, 256>>>(W2, N);
    k_compact_edges<<<nb_e, 256>>>(src, dst, E);

    // ---- CSR build (stage 2) ----
    k_deg2<<<2048, 256>>>();
    k_rows<<<(K1 + 255) / 256, 256>>>(1, K1);
    k_scatter2<<<2048, 256>>>();

    // ---- stage 2: pull-agg + BN + LReLU ----
    k_pullagg32<<<(K1 * 32 + 255) / 256, 256>>>(K1);
    k_bnstats<32><<<512, 256>>>(K1);
    k_bnapply<32><<<(K1 + 255) / 256, 256>>>(K1, g2, be2, Wr2, br2, Wroot2);

    // ---- stage 2 score + top-k select ----
    k_pullscore2<<<(K1 * 32 + 255) / 256, 256>>>(K1);
    k_keyhist0<<<128, 256>>>(1, K1);
    k_scan16<<<1, 1024>>>(1, 0);
    for (int p = 1; p < 4; p++) {
        k_hist16<<<64, 256>>>(1, K1, p);
        k_scan16<<<1, 1024>>>(1, p);
    }

    // ---- global add pool + MLP ----
    k_pool<<<256, 256>>>(K1);
    k_mlp<<<1, 32>>>(fw1, fb1, fw2, fb2, fw3, fb3, out);
}